// round 16
// baseline (speedup 1.0000x reference)
#include <cuda_runtime.h>
#include <cuda_bf16.h>
#include <math.h>
#include <stdint.h>

// ---------------------------------------------------------------------------
// Problem constants (B=2, H=W=64, C=256, nh=4, hd=64, k=7)
// ---------------------------------------------------------------------------
#define NTOK   8192
#define CDIM   256
#define GK     256
#define QKVN   768
#define FFN    512
#define KS     7
#define KK     49

// ---------------------------------------------------------------------------
// Scratch (__device__ globals; allocation forbidden)
// ---------------------------------------------------------------------------
__device__ __nv_bfloat16 g_h   [NTOK * CDIM];
__device__ __nv_bfloat16 g_qkv [NTOK * QKVN];
__device__ __nv_bfloat16 g_attn[NTOK * CDIM];
__device__ float         g_x1  [NTOK * CDIM];
__device__ __nv_bfloat16 g_wqkvT[QKVN * GK];
__device__ __nv_bfloat16 g_wprojT[CDIM * GK];
__device__ __nv_bfloat16 g_ff1T [FFN  * GK];   // PERMUTED column order
__device__ __nv_bfloat16 g_ff2T [CDIM * GK];

// ---------------------------------------------------------------------------
// PTX helpers
// ---------------------------------------------------------------------------
__device__ __forceinline__ uint32_t smem_u32(const void* p) {
    uint32_t a;
    asm("{ .reg .u64 t; cvta.to.shared.u64 t, %1; cvt.u32.u64 %0, t; }"
        : "=r"(a) : "l"(p));
    return a;
}
#define LDMATRIX_X4(r0, r1, r2, r3, a) \
    asm volatile("ldmatrix.sync.aligned.m8n8.x4.shared.b16 {%0,%1,%2,%3}, [%4];" \
                 : "=r"(r0), "=r"(r1), "=r"(r2), "=r"(r3) : "r"(a))
#define LDMATRIX_X4_TRANS(r0, r1, r2, r3, a) \
    asm volatile("ldmatrix.sync.aligned.m8n8.x4.trans.shared.b16 {%0,%1,%2,%3}, [%4];" \
                 : "=r"(r0), "=r"(r1), "=r"(r2), "=r"(r3) : "r"(a))
#define MMA_BF16(d, a, b) \
    asm volatile("mma.sync.aligned.m16n8k16.row.col.f32.bf16.bf16.f32 " \
                 "{%0,%1,%2,%3}, {%4,%5,%6,%7}, {%8,%9}, {%0,%1,%2,%3};" \
                 : "+f"((d)[0]), "+f"((d)[1]), "+f"((d)[2]), "+f"((d)[3]) \
                 : "r"((a)[0]), "r"((a)[1]), "r"((a)[2]), "r"((a)[3]), \
                   "r"((b)[0]), "r"((b)[1]))
#define CP_ASYNC16(dst, src) \
    asm volatile("cp.async.cg.shared.global [%0], [%1], 16;" :: "r"(dst), "l"(src))
#define CP_COMMIT() asm volatile("cp.async.commit_group;" ::: "memory")
#define CP_WAIT(n)  asm volatile("cp.async.wait_group %0;" :: "n"(n) : "memory")

__device__ __forceinline__ uint32_t swz(uint32_t off) { return off ^ ((off >> 3) & 0x70); }
__device__ __forceinline__ uint32_t packbf(float a, float b) {
    __nv_bfloat162 h = __floats2bfloat162_rn(a, b);
    return *reinterpret_cast<uint32_t*>(&h);
}
// ff1 permutation: out col n -> source col of ff1_w
__device__ __forceinline__ int ff1_src(int n) {
    const int within = n & 127, blk = n >> 7;
    return (within < 64) ? (blk * 64 + within) : (256 + blk * 64 + within - 64);
}

// ---------------------------------------------------------------------------
// prep_kernel: weight transposes (ff1 permuted) + rmsnorm1+rope, ONE launch.
// ---------------------------------------------------------------------------
__global__ void prep_kernel(const float* __restrict__ w0, __nv_bfloat16* __restrict__ o0,
                            const float* __restrict__ w1, __nv_bfloat16* __restrict__ o1,
                            const float* __restrict__ w2, __nv_bfloat16* __restrict__ o2,
                            const float* __restrict__ w3, __nv_bfloat16* __restrict__ o3,
                            const float* __restrict__ x,  const float* __restrict__ n1w,
                            __nv_bfloat16* __restrict__ h)
{
    const int bx  = blockIdx.x;
    const int tid = threadIdx.x;
    __shared__ float t[32][33];
    __shared__ float red[2][4];

    if (bx < 448) {
        const int wtile = bx >> 3;
        const int k0    = (bx & 7) * 32;
        const float* w; __nv_bfloat16* o; int N, nb; bool perm = false;
        if      (wtile < 24) { w = w0; o = o0; N = QKVN; nb = wtile;      }
        else if (wtile < 32) { w = w1; o = o1; N = CDIM; nb = wtile - 24; }
        else if (wtile < 48) { w = w2; o = o2; N = FFN;  nb = wtile - 32; perm = true; }
        else                 { w = w3; o = o3; N = CDIM; nb = wtile - 48; }

        const int n0 = nb * 32;
        const int s0 = perm ? ff1_src(n0) : n0;
        const int tx = tid & 31, ty = tid >> 5;
        #pragma unroll
        for (int i = 0; i < 32; i += 8)
            t[ty + i][tx] = w[(size_t)(k0 + ty + i) * N + s0 + tx];
        __syncthreads();
        #pragma unroll
        for (int i = 0; i < 32; i += 8)
            o[(size_t)(n0 + ty + i) * GK + k0 + tx] = __float2bfloat16(t[tx][ty + i]);
        return;
    }

    // ---- rmsnorm1 + rope: 2 tokens per block ----
    const int tok  = (bx - 448) * 2 + (tid >> 7);
    const int i    = tid & 127;
    const int half = tid >> 7;
    float2 v = reinterpret_cast<const float2*>(x + (size_t)tok * CDIM)[i];

    float ss = v.x * v.x + v.y * v.y;
    #pragma unroll
    for (int off = 16; off; off >>= 1)
        ss += __shfl_xor_sync(0xffffffffu, ss, off);
    if ((i & 31) == 0) red[half][i >> 5] = ss;
    __syncthreads();
    const float r = rsqrtf((red[half][0] + red[half][1] + red[half][2] + red[half][3])
                           * (1.0f / CDIM) + 1e-6f);

    const float2 wv = reinterpret_cast<const float2*>(n1w)[i];
    float a = v.x * r * wv.x;
    float b = v.y * r * wv.y;

    const int yy = (tok >> 6) & 63;
    const int xx = tok & 63;
    const int j  = i & 63;
    const float pos = (i < 64) ? (float)yy : (float)xx;
    const float inv = exp2f((float)j * (-13.28771237954945f / 64.0f));
    float c, s;
    sincosf(pos * inv, &s, &c);
    reinterpret_cast<__nv_bfloat162*>(h + (size_t)tok * CDIM)[i] =
        __floats2bfloat162_rn(a * c - b * s, a * s + b * c);
}

// ---------------------------------------------------------------------------
// Generic mma.sync bf16 GEMM: BM=64, BN=64, 128 threads, ring 32KB (R10).
// Used for the qkv GEMM (bf16 out).
// ---------------------------------------------------------------------------
#define GS_STAGE 16384u
#define SM_SIZE  32768

__global__ __launch_bounds__(128, 5)
void gemm_mma_kernel(const __nv_bfloat16* __restrict__ A,
                     const __nv_bfloat16* __restrict__ Bt,
                     __nv_bfloat16* __restrict__ Cb,
                     int N)
{
    extern __shared__ __align__(1024) char smem[];
    const uint32_t sb = smem_u32(smem);
    const int tid  = threadIdx.x;
    const int wid  = tid >> 5;
    const int lane = tid & 31;
    const int bm   = blockIdx.y * 64;
    const int bn   = blockIdx.x * 64;
    const int wm   = wid & 1;
    const int wn   = wid >> 1;
    const int lrow = tid >> 3;
    const int lch  = tid & 7;

    #define LOAD_CHUNK(kc, stage) do {                                           \
        const uint32_t s0 = (uint32_t)(stage) * GS_STAGE;                        \
        _Pragma("unroll")                                                        \
        for (int it = 0; it < 4; it++) {                                         \
            const int row = it * 16 + lrow;                                      \
            uint32_t off = swz((uint32_t)row * 128u + (uint32_t)lch * 16u);      \
            CP_ASYNC16(sb + s0 + off,                                            \
                       A  + (size_t)(bm + row) * GK + (kc) * 64 + lch * 8);      \
            CP_ASYNC16(sb + s0 + 8192u + off,                                    \
                       Bt + (size_t)(bn + row) * GK + (kc) * 64 + lch * 8);      \
        }                                                                        \
        CP_COMMIT();                                                             \
    } while (0)

    LOAD_CHUNK(0, 0);
    LOAD_CHUNK(1, 1);

    float acc[2][4][4] = {};
    const int mtx = lane >> 3;
    const int l7  = lane & 7;

    #pragma unroll
    for (int kc = 0; kc < 4; kc++) {
        if (kc < 3) CP_WAIT(1); else CP_WAIT(0);
        __syncthreads();
        const uint32_t sA = sb + (uint32_t)(kc & 1) * GS_STAGE;
        const uint32_t sB = sA + 8192u;

        #pragma unroll
        for (int s16 = 0; s16 < 4; s16++) {
            const int chunk0 = s16 * 2;
            uint32_t af[2][4];
            #pragma unroll
            for (int mt = 0; mt < 2; mt++) {
                const int row   = wm * 32 + mt * 16 + (mtx & 1) * 8 + l7;
                const int chunk = chunk0 + (mtx >> 1);
                LDMATRIX_X4(af[mt][0], af[mt][1], af[mt][2], af[mt][3],
                            sA + swz((uint32_t)row * 128u + (uint32_t)chunk * 16u));
            }
            uint32_t bf[4][2];
            #pragma unroll
            for (int pair = 0; pair < 2; pair++) {
                const int nrow  = wn * 32 + pair * 16 + (mtx >> 1) * 8 + l7;
                const int chunk = chunk0 + (mtx & 1);
                LDMATRIX_X4(bf[pair * 2][0], bf[pair * 2][1],
                            bf[pair * 2 + 1][0], bf[pair * 2 + 1][1],
                            sB + swz((uint32_t)nrow * 128u + (uint32_t)chunk * 16u));
            }
            #pragma unroll
            for (int mt = 0; mt < 2; mt++)
                #pragma unroll
                for (int nt = 0; nt < 4; nt++)
                    MMA_BF16(acc[mt][nt], af[mt], bf[nt]);
        }
        __syncthreads();
        if (kc < 2) LOAD_CHUNK(kc + 2, kc & 1);
    }
    #undef LOAD_CHUNK

    const int rbase = bm + wm * 32 + (lane >> 2);
    const int cbase = bn + wn * 32 + (lane & 3) * 2;
    #pragma unroll
    for (int mt = 0; mt < 2; mt++) {
        #pragma unroll
        for (int half = 0; half < 2; half++) {
            const int row = rbase + mt * 16 + half * 8;
            #pragma unroll
            for (int nt = 0; nt < 4; nt++) {
                const int col = cbase + nt * 8;
                *reinterpret_cast<__nv_bfloat162*>(&Cb[(size_t)row * N + col]) =
                    __floats2bfloat162_rn(acc[mt][nt][half * 2],
                                          acc[mt][nt][half * 2 + 1]);
            }
        }
    }
}

// ---------------------------------------------------------------------------
// FFN megakernel v2: 512 threads (16 warps), warp tile 16 rows x 16 cols.
// Per CTA of 64 token rows:
//   x1 = x + attn@WprojT + bproj;  n2 = rmsnorm(x1);  g = geglu(n2@ff1T_perm);
//   out = x1 + g@ff2T + ff2b.  16 weight blocks streamed, 2-stage ring.
// ---------------------------------------------------------------------------
#define FM_A    0u
#define FM_W    32768u
#define FM_N2   98304u
#define FM_G    131072u
#define FM_SS   163840u
#define FM_SIZE 164864

__global__ __launch_bounds__(512, 1)
void ffn_mega_kernel(const __nv_bfloat16* __restrict__ Aattn,
                     const float* __restrict__ x,
                     const __nv_bfloat16* __restrict__ WprojT,
                     const float* __restrict__ bproj,
                     const float* __restrict__ n2w,
                     const __nv_bfloat16* __restrict__ Wff1T,
                     const float* __restrict__ ff1b,
                     const __nv_bfloat16* __restrict__ Wff2T,
                     const float* __restrict__ ff2b,
                     float* __restrict__ X1,
                     float* __restrict__ OUT)
{
    extern __shared__ __align__(1024) char smem[];
    const uint32_t sb = smem_u32(smem);
    float* ssq_sm = reinterpret_cast<float*>(smem + FM_SS);   // [64][4]

    const int tid  = threadIdx.x;
    const int wid  = tid >> 5;
    const int lane = tid & 31;
    const int bm   = blockIdx.x * 64;
    const int wm   = wid & 3;            // row band (16 rows)
    const int wn   = wid >> 2;           // col group (16 cols within 64)
    const int mtx  = lane >> 3;
    const int l7   = lane & 7;

    // ---- A (attn) tile load: 64 x 256 bf16 = 2048 16B chunks, 4 iters ----
    #pragma unroll
    for (int it = 0; it < 4; it++) {
        const int idx = it * 512 + tid;
        const int r = idx >> 5, c = idx & 31;
        uint32_t off = swz((uint32_t)(c >> 3) * 8192u + (uint32_t)r * 128u
                           + (uint32_t)(c & 7) * 16u);
        CP_ASYNC16(sb + FM_A + off,
                   Aattn + (size_t)(bm + r) * GK + (c >> 3) * 64 + (c & 7) * 8);
    }
    #define WSRC(i) ((i) < 4 ? WprojT + (size_t)(i) * 64 * GK                   \
                   : (i) < 12 ? Wff1T + (size_t)((i) - 4) * 64 * GK             \
                              : Wff2T + (size_t)((i) - 12) * 64 * GK)
    #define LOAD_W(i, stage) do {                                                \
        const __nv_bfloat16* _w = WSRC(i);                                       \
        const uint32_t s0 = FM_W + (uint32_t)(stage) * 32768u;                   \
        _Pragma("unroll")                                                        \
        for (int it = 0; it < 4; it++) {                                         \
            const int idx = it * 512 + tid;                                      \
            const int r = idx >> 5, c = idx & 31;                                \
            uint32_t off = swz((uint32_t)(c >> 3) * 8192u + (uint32_t)r * 128u   \
                               + (uint32_t)(c & 7) * 16u);                       \
            CP_ASYNC16(sb + s0 + off,                                            \
                       _w + (size_t)r * GK + (c >> 3) * 64 + (c & 7) * 8);       \
        }                                                                        \
        CP_COMMIT();                                                             \
    } while (0)

    LOAD_W(0, 0);
    LOAD_W(1, 1);

    const int rl = wm * 16 + (lane >> 2);       // local rows rl, rl+8
    const int cl = wn * 16 + (lane & 3) * 2;    // local col base within 64
    float ssq0 = 0.0f, ssq1 = 0.0f;
    float accG[2][4];

    #pragma unroll 1
    for (int i = 0; i < 16; i++) {
        if (i < 15) CP_WAIT(1); else CP_WAIT(0);
        __syncthreads();

        const uint32_t sW = sb + FM_W + (uint32_t)(i & 1) * 32768u;
        const uint32_t sA = sb + ((i < 4) ? FM_A : (i < 12) ? FM_N2 : FM_G);

        float acc[2][4] = {};
        #pragma unroll
        for (int k16 = 0; k16 < 16; k16++) {
            const uint32_t blk = (uint32_t)(k16 >> 2) * 8192u;
            const int      ch0 = (k16 & 3) * 2;
            uint32_t af[4];
            {
                const int row   = wm * 16 + (mtx & 1) * 8 + l7;
                const int chunk = ch0 + (mtx >> 1);
                LDMATRIX_X4(af[0], af[1], af[2], af[3],
                            sA + swz(blk + (uint32_t)row * 128u + (uint32_t)chunk * 16u));
            }
            uint32_t bf[2][2];
            {
                const int nrow  = wn * 16 + (mtx >> 1) * 8 + l7;
                const int chunk = ch0 + (mtx & 1);
                LDMATRIX_X4(bf[0][0], bf[0][1], bf[1][0], bf[1][1],
                            sW + swz(blk + (uint32_t)nrow * 128u + (uint32_t)chunk * 16u));
            }
            MMA_BF16(acc[0], af, bf[0]);
            MMA_BF16(acc[1], af, bf[1]);
        }
        __syncthreads();                 // all sW reads done before overwrite
        if (i < 14) LOAD_W(i + 2, i & 1);

        // ---------------- epilogues ----------------
        if (i < 4) {
            #pragma unroll
            for (int half = 0; half < 2; half++) {
                const int rloc = rl + half * 8;
                const int rowg = bm + rloc;
                float* sacc = half ? &ssq1 : &ssq0;
                #pragma unroll
                for (int nt = 0; nt < 2; nt++) {
                    const int colg = i * 64 + cl + nt * 8;
                    float ox = acc[nt][half * 2]     + bproj[colg];
                    float oy = acc[nt][half * 2 + 1] + bproj[colg + 1];
                    const size_t idx = (size_t)rowg * CDIM + colg;
                    const float2 rr = *reinterpret_cast<const float2*>(&x[idx]);
                    ox += rr.x; oy += rr.y;
                    *reinterpret_cast<float2*>(&X1[idx]) = make_float2(ox, oy);
                    *sacc += ox * ox + oy * oy;
                    const int within = cl + nt * 8;
                    *reinterpret_cast<uint32_t*>(smem + FM_N2 +
                        swz((uint32_t)i * 8192u + (uint32_t)rloc * 128u
                            + (uint32_t)within * 2u)) = packbf(ox, oy);
                }
            }
            if (i == 3) {
                float v0 = ssq0, v1 = ssq1;
                v0 += __shfl_xor_sync(0xffffffffu, v0, 1);
                v0 += __shfl_xor_sync(0xffffffffu, v0, 2);
                v1 += __shfl_xor_sync(0xffffffffu, v1, 1);
                v1 += __shfl_xor_sync(0xffffffffu, v1, 2);
                if ((lane & 3) == 0) {
                    ssq_sm[rl * 4 + wn]       = v0;
                    ssq_sm[(rl + 8) * 4 + wn] = v1;
                }
                __syncthreads();
                // scale N2 smem in place: 512 threads, 8 per row
                const int row = tid >> 3;
                const int q   = tid & 7;
                const int cs  = q >> 1;
                const int kh  = (q & 1) * 4;
                const float rr = rsqrtf((ssq_sm[row * 4 + 0] + ssq_sm[row * 4 + 1]
                                       + ssq_sm[row * 4 + 2] + ssq_sm[row * 4 + 3])
                                        * (1.0f / CDIM) + 1e-6f);
                #pragma unroll
                for (int k = 0; k < 4; k++) {
                    const uint32_t addr = FM_N2 +
                        swz((uint32_t)cs * 8192u + (uint32_t)row * 128u
                            + (uint32_t)(kh + k) * 16u);
                    uint4 v = *reinterpret_cast<uint4*>(smem + addr);
                    uint32_t* vp = reinterpret_cast<uint32_t*>(&v);
                    const int col0 = cs * 64 + (kh + k) * 8;
                    #pragma unroll
                    for (int e = 0; e < 4; e++) {
                        __nv_bfloat162 bv = *reinterpret_cast<__nv_bfloat162*>(&vp[e]);
                        const float2 f = __bfloat1622float2(bv);
                        const float2 wv = *reinterpret_cast<const float2*>(
                            &n2w[col0 + e * 2]);
                        vp[e] = packbf(f.x * rr * wv.x, f.y * rr * wv.y);
                    }
                    *reinterpret_cast<uint4*>(smem + addr) = v;
                }
                __syncthreads();
            }
        } else if (i < 12) {
            const int fb = i - 4;
            #pragma unroll
            for (int half = 0; half < 2; half++)
                #pragma unroll
                for (int nt = 0; nt < 2; nt++) {
                    const int colp = fb * 64 + cl + nt * 8;
                    acc[nt][half * 2]     += ff1b[ff1_src(colp)];
                    acc[nt][half * 2 + 1] += ff1b[ff1_src(colp + 1)];
                }
            if ((fb & 1) == 0) {
                #pragma unroll
                for (int nt = 0; nt < 2; nt++)
                    #pragma unroll
                    for (int e = 0; e < 4; e++) accG[nt][e] = acc[nt][e];
            } else {
                const int p = fb >> 1;
                #pragma unroll
                for (int half = 0; half < 2; half++) {
                    const int rloc = rl + half * 8;
                    #pragma unroll
                    for (int nt = 0; nt < 2; nt++) {
                        const float g0 = accG[nt][half * 2];
                        const float g1 = accG[nt][half * 2 + 1];
                        const float e0 = 0.5f * g0 *
                            (1.0f + erff(g0 * 0.70710678118654752f));
                        const float e1 = 0.5f * g1 *
                            (1.0f + erff(g1 * 0.70710678118654752f));
                        const int within = cl + nt * 8;
                        *reinterpret_cast<uint32_t*>(smem + FM_G +
                            swz((uint32_t)p * 8192u + (uint32_t)rloc * 128u
                                + (uint32_t)within * 2u)) =
                            packbf(e0 * acc[nt][half * 2],
                                   e1 * acc[nt][half * 2 + 1]);
                    }
                }
            }
        } else {
            const int ob = i - 12;
            #pragma unroll
            for (int half = 0; half < 2; half++) {
                const int rowg = bm + rl + half * 8;
                #pragma unroll
                for (int nt = 0; nt < 2; nt++) {
                    const int colg = ob * 64 + cl + nt * 8;
                    const size_t idx = (size_t)rowg * CDIM + colg;
                    const float2 rr = *reinterpret_cast<const float2*>(&X1[idx]);
                    *reinterpret_cast<float2*>(&OUT[idx]) =
                        make_float2(acc[nt][half * 2]     + ff2b[colg]     + rr.x,
                                    acc[nt][half * 2 + 1] + ff2b[colg + 1] + rr.y);
                }
            }
        }
    }
    #undef LOAD_W
    #undef WSRC
}

// ---------------------------------------------------------------------------
// Neighborhood attention, 4x8 token tile, halo 10x14 -> 160 kv (R12/R13).
// ---------------------------------------------------------------------------
#define AT_Q    0
#define AT_K    4096
#define AT_V    24576
#define AT_RED  4096
#define AT_MAX  45056
#define AT_SUM  45312
#define AT_SIZE 45568
#define REDW    68

__global__ __launch_bounds__(128, 5)
void attn_mma_kernel(const __nv_bfloat16* __restrict__ qkv,
                     __nv_bfloat16* __restrict__ out)
{
    extern __shared__ __align__(1024) char smem[];
    const uint32_t sb = smem_u32(smem);
    float* smax = reinterpret_cast<float*>(smem + AT_MAX);
    float* ssum = reinterpret_cast<float*>(smem + AT_SUM);
    float* sred = reinterpret_cast<float*>(smem + AT_RED);

    const int tid  = threadIdx.x;
    const int wid  = tid >> 5;
    const int lane = tid & 31;
    const int head = blockIdx.y;
    const int b    = blockIdx.z;
    const int ty0  = (blockIdx.x >> 3) * 4;
    const int tx0  = (blockIdx.x & 7) * 8;
    const int ny0  = min(max(ty0 - 3, 0), 54);
    const int nx0  = min(max(tx0 - 3, 0), 50);

    const __nv_bfloat16* base = qkv + (size_t)b * 4096 * QKVN + head * 64;

    #pragma unroll
    for (int i = 0; i < 2; i++) {
        const int idx = i * 128 + tid;
        const int m = idx >> 3, ch = idx & 7;
        const int y = ty0 + (m >> 3), x = tx0 + (m & 7);
        uint32_t off = swz((uint32_t)m * 128u + (uint32_t)ch * 16u);
        CP_ASYNC16(sb + AT_Q + off, base + (size_t)(y * 64 + x) * QKVN + ch * 8);
    }
    CP_COMMIT();
    #pragma unroll
    for (int i = 0; i < 10; i++) {
        const int idx = i * 128 + tid;
        const int kv = idx >> 3, ch = idx & 7;
        const int r = kv >> 4, c = kv & 15;
        uint32_t off = swz((uint32_t)kv * 128u + (uint32_t)ch * 16u);
        if (c < 14)
            CP_ASYNC16(sb + AT_K + off,
                       base + (size_t)((ny0 + r) * 64 + nx0 + c) * QKVN + CDIM + ch * 8);
        else
            *reinterpret_cast<uint4*>(smem + AT_K + off) = make_uint4(0, 0, 0, 0);
    }
    CP_COMMIT();
    #pragma unroll
    for (int i = 0; i < 10; i++) {
        const int idx = i * 128 + tid;
        const int kv = idx >> 3, ch = idx & 7;
        const int r = kv >> 4, c = kv & 15;
        uint32_t off = swz((uint32_t)kv * 128u + (uint32_t)ch * 16u);
        if (c < 14)
            CP_ASYNC16(sb + AT_V + off,
                       base + (size_t)((ny0 + r) * 64 + nx0 + c) * QKVN + 2 * CDIM + ch * 8);
        else
            *reinterpret_cast<uint4*>(smem + AT_V + off) = make_uint4(0, 0, 0, 0);
    }
    CP_COMMIT();

    const int wm  = wid & 1;
    const int wn  = wid >> 1;
    const int mtx = lane >> 3;
    const int l7  = lane & 7;

    CP_WAIT(1);
    __syncthreads();

    uint32_t af[4][4];
    #pragma unroll
    for (int k16 = 0; k16 < 4; k16++) {
        const int row   = wm * 16 + (mtx & 1) * 8 + l7;
        const int chunk = k16 * 2 + (mtx >> 1);
        LDMATRIX_X4(af[k16][0], af[k16][1], af[k16][2], af[k16][3],
                    sb + AT_Q + swz((uint32_t)row * 128u + (uint32_t)chunk * 16u));
    }

    float acc[10][4] = {};
    #pragma unroll
    for (int k16 = 0; k16 < 4; k16++) {
        #pragma unroll
        for (int pair = 0; pair < 5; pair++) {
            const int nrow  = wn * 80 + pair * 16 + (mtx >> 1) * 8 + l7;
            const int chunk = k16 * 2 + (mtx & 1);
            uint32_t b0, b1, b2, b3;
            LDMATRIX_X4(b0, b1, b2, b3,
                        sb + AT_K + swz((uint32_t)nrow * 128u + (uint32_t)chunk * 16u));
            uint32_t bfa[2] = {b0, b1}, bfb[2] = {b2, b3};
            MMA_BF16(acc[pair * 2],     af[k16], bfa);
            MMA_BF16(acc[pair * 2 + 1], af[k16], bfb);
        }
    }

    const int row0 = wm * 16 + (lane >> 2);
    const int row1 = row0 + 8;
    const int y_a = ty0 + (row0 >> 3), x_a = tx0 + (row0 & 7);
    const int y_b = ty0 + (row1 >> 3), x_b = tx0 + (row1 & 7);
    const int rlo_a = min(max(y_a - 3, 0), 57) - ny0;
    const int clo_a = min(max(x_a - 3, 0), 57) - nx0;
    const int rlo_b = min(max(y_b - 3, 0), 57) - ny0;
    const int clo_b = min(max(x_b - 3, 0), 57) - nx0;

    uint32_t vm_a = 0, vm_b = 0;
    #pragma unroll
    for (int nt = 0; nt < 10; nt++) {
        #pragma unroll
        for (int j = 0; j < 2; j++) {
            const int n = wn * 80 + nt * 8 + (lane & 3) * 2 + j;
            const int r = n >> 4, c = n & 15;
            if (c < 14 && (unsigned)(r - rlo_a) < 7u && (unsigned)(c - clo_a) < 7u)
                vm_a |= 1u << (nt * 2 + j);
            if (c < 14 && (unsigned)(r - rlo_b) < 7u && (unsigned)(c - clo_b) < 7u)
                vm_b |= 1u << (nt * 2 + j);
        }
    }

    float mx_a = -3e38f, mx_b = -3e38f;
    #pragma unroll
    for (int nt = 0; nt < 10; nt++) {
        #pragma unroll
        for (int j = 0; j < 2; j++) {
            if (vm_a & (1u << (nt * 2 + j))) mx_a = fmaxf(mx_a, acc[nt][j]);
            if (vm_b & (1u << (nt * 2 + j))) mx_b = fmaxf(mx_b, acc[nt][2 + j]);
        }
    }
    mx_a = fmaxf(mx_a, __shfl_xor_sync(0xffffffffu, mx_a, 1));
    mx_a = fmaxf(mx_a, __shfl_xor_sync(0xffffffffu, mx_a, 2));
    mx_b = fmaxf(mx_b, __shfl_xor_sync(0xffffffffu, mx_b, 1));
    mx_b = fmaxf(mx_b, __shfl_xor_sync(0xffffffffu, mx_b, 2));
    if ((lane & 3) == 0) {
        smax[row0 * 2 + wn] = mx_a;
        smax[row1 * 2 + wn] = mx_b;
    }
    __syncthreads();
    const float M_a = fmaxf(smax[row0 * 2], smax[row0 * 2 + 1]);
    const float M_b = fmaxf(smax[row1 * 2], smax[row1 * 2 + 1]);

    const float SC = 0.18033688011112042f;
    float sm_a = 0.0f, sm_b = 0.0f;
    #pragma unroll
    for (int nt = 0; nt < 10; nt++) {
        #pragma unroll
        for (int j = 0; j < 2; j++) {
            float ea = (vm_a & (1u << (nt * 2 + j)))
                     ? exp2f((acc[nt][j] - M_a) * SC) : 0.0f;
            float eb = (vm_b & (1u << (nt * 2 + j)))
                     ? exp2f((acc[nt][2 + j] - M_b) * SC) : 0.0f;
            acc[nt][j] = ea; acc[nt][2 + j] = eb;
            sm_a += ea; sm_b += eb;
        }
    }
    sm_a += __shfl_xor_sync(0xffffffffu, sm_a, 1);
    sm_a += __shfl_xor_sync(0xffffffffu, sm_a, 2);
    sm_b += __shfl_xor_sync(0xffffffffu, sm_b, 1);
    sm_b += __shfl_xor_sync(0xffffffffu, sm_b, 2);
    if ((lane & 3) == 0) {
        ssum[row0 * 2 + wn] = sm_a;
        ssum[row1 * 2 + wn] = sm_b;
    }

    uint32_t pf[5][4];
    #pragma unroll
    for (int s = 0; s < 5; s++) {
        pf[s][0] = packbf(acc[2 * s][0],     acc[2 * s][1]);
        pf[s][1] = packbf(acc[2 * s][2],     acc[2 * s][3]);
        pf[s][2] = packbf(acc[2 * s + 1][0], acc[2 * s + 1][1]);
        pf[s][3] = packbf(acc[2 * s + 1][2], acc[2 * s + 1][3]);
    }

    CP_WAIT(0);
    __syncthreads();

    float accO[8][4] = {};
    #pragma unroll
    for (int s = 0; s < 5; s++) {
        uint32_t vf[8][2];
        #pragma unroll
        for (int g2 = 0; g2 < 4; g2++) {
            const int kvrow = wn * 80 + s * 16 + (lane & 15);
            const int colb  = (g2 * 16 + (lane >> 4) * 8) * 2;
            LDMATRIX_X4_TRANS(vf[g2 * 2][0], vf[g2 * 2][1],
                              vf[g2 * 2 + 1][0], vf[g2 * 2 + 1][1],
                              sb + AT_V + swz((uint32_t)kvrow * 128u + (uint32_t)colb));
        }
        #pragma unroll
        for (int nt = 0; nt < 8; nt++)
            MMA_BF16(accO[nt], pf[s], vf[nt]);
    }

    if (wn == 1) {
        #pragma unroll
        for (int nt = 0; nt < 8; nt++) {
            const int col = nt * 8 + (lane & 3) * 2;
            *reinterpret_cast<float2*>(&sred[row0 * REDW + col]) =
                make_float2(accO[nt][0], accO[nt][1]);
            *reinterpret_cast<float2*>(&sred[row1 * REDW + col]) =
                make_float2(accO[nt][2], accO[nt][3]);
        }
    }
    __syncthreads();

    if (wn == 0) {
        const float inv_a = 1.0f / (ssum[row0 * 2] + ssum[row0 * 2 + 1]);
        const float inv_b = 1.0f / (ssum[row1 * 2] + ssum[row1 * 2 + 1]);
        const size_t t_a = (size_t)b * 4096 + (size_t)(y_a * 64 + x_a);
        const size_t t_b = (size_t)b * 4096 + (size_t)(y_b * 64 + x_b);
        #pragma unroll
        for (int nt = 0; nt < 8; nt++) {
            const int col = nt * 8 + (lane & 3) * 2;
            const float2 ra = *reinterpret_cast<const float2*>(&sred[row0 * REDW + col]);
            const float2 rb = *reinterpret_cast<const float2*>(&sred[row1 * REDW + col]);
            *reinterpret_cast<__nv_bfloat162*>(out + t_a * CDIM + head * 64 + col) =
                __floats2bfloat162_rn((accO[nt][0] + ra.x) * inv_a,
                                      (accO[nt][1] + ra.y) * inv_a);
            *reinterpret_cast<__nv_bfloat162*>(out + t_b * CDIM + head * 64 + col) =
                __floats2bfloat162_rn((accO[nt][2] + rb.x) * inv_b,
                                      (accO[nt][3] + rb.y) * inv_b);
        }
    }
}

// ---------------------------------------------------------------------------
// Launch: 4 kernels.
// ---------------------------------------------------------------------------
extern "C" void kernel_launch(void* const* d_in, const int* in_sizes, int n_in,
                              void* d_out, int out_size)
{
    const float* x       = (const float*)d_in[0];
    const float* norm1_w = (const float*)d_in[1];
    const float* norm2_w = (const float*)d_in[2];
    const float* w_qkv   = (const float*)d_in[3];
    const float* w_proj  = (const float*)d_in[4];
    const float* b_proj  = (const float*)d_in[5];
    const float* ff1_w   = (const float*)d_in[6];
    const float* ff1_b   = (const float*)d_in[7];
    const float* ff2_w   = (const float*)d_in[8];
    const float* ff2_b   = (const float*)d_in[9];
    float* out = (float*)d_out;

    __nv_bfloat16 *p_h, *p_qkv, *p_attn;
    __nv_bfloat16 *p_wqkvT, *p_wprojT, *p_ff1T, *p_ff2T;
    float *p_x1;
    cudaGetSymbolAddress((void**)&p_h,      g_h);
    cudaGetSymbolAddress((void**)&p_qkv,    g_qkv);
    cudaGetSymbolAddress((void**)&p_attn,   g_attn);
    cudaGetSymbolAddress((void**)&p_x1,     g_x1);
    cudaGetSymbolAddress((void**)&p_wqkvT,  g_wqkvT);
    cudaGetSymbolAddress((void**)&p_wprojT, g_wprojT);
    cudaGetSymbolAddress((void**)&p_ff1T,   g_ff1T);
    cudaGetSymbolAddress((void**)&p_ff2T,   g_ff2T);

    cudaFuncSetAttribute(gemm_mma_kernel,
                         cudaFuncAttributeMaxDynamicSharedMemorySize, SM_SIZE);
    cudaFuncSetAttribute(attn_mma_kernel,
                         cudaFuncAttributeMaxDynamicSharedMemorySize, AT_SIZE);
    cudaFuncSetAttribute(ffn_mega_kernel,
                         cudaFuncAttributeMaxDynamicSharedMemorySize, FM_SIZE);

    // 1. weight transposes (ff1 permuted) + rmsnorm1+rope
    prep_kernel<<<448 + NTOK / 2, 256>>>(
        w_qkv, p_wqkvT, w_proj, p_wprojT, ff1_w, p_ff1T, ff2_w, p_ff2T,
        x, norm1_w, p_h);

    // 2. qkv = h @ w_qkv -> bf16
    gemm_mma_kernel<<<dim3(QKVN / 64, NTOK / 64), 128, SM_SIZE>>>(
        p_h, p_wqkvT, p_qkv, QKVN);

    // 3. attention (4x8 tiles) -> bf16
    attn_mma_kernel<<<dim3(128, 4, 2), 128, AT_SIZE>>>(p_qkv, p_attn);

    // 4. full FFN (16 warps): proj+norm2+ff1+geglu+ff2
    ffn_mega_kernel<<<NTOK / 64, 512, FM_SIZE>>>(
        p_attn, x, p_wprojT, b_proj, norm2_w,
        p_ff1T, ff1_b, p_ff2T, ff2_b, p_x1, out);
}

// round 17
// speedup vs baseline: 1.1510x; 1.1510x over previous
#include <cuda_runtime.h>
#include <cuda_bf16.h>
#include <math.h>
#include <stdint.h>

// ---------------------------------------------------------------------------
// Problem constants (B=2, H=W=64, C=256, nh=4, hd=64, k=7)
// ---------------------------------------------------------------------------
#define NTOK   8192
#define CDIM   256
#define GK     256
#define QKVN   768
#define FFN    512
#define KS     7
#define KK     49

// ---------------------------------------------------------------------------
// Scratch (__device__ globals; allocation forbidden)
// ---------------------------------------------------------------------------
__device__ __nv_bfloat16 g_h   [NTOK * CDIM];
__device__ __nv_bfloat16 g_qkv [NTOK * QKVN];
__device__ __nv_bfloat16 g_attn[NTOK * CDIM];
__device__ float         g_x1  [NTOK * CDIM];
__device__ __nv_bfloat16 g_n2  [NTOK * CDIM];
__device__ __nv_bfloat16 g_g   [NTOK * CDIM];
__device__ __nv_bfloat16 g_wqkvT[QKVN * GK];
__device__ __nv_bfloat16 g_wprojT[CDIM * GK];
__device__ __nv_bfloat16 g_ff1T [FFN  * GK];   // PERMUTED column order
__device__ __nv_bfloat16 g_ff2T [CDIM * GK];

// ---------------------------------------------------------------------------
// PTX helpers
// ---------------------------------------------------------------------------
__device__ __forceinline__ uint32_t smem_u32(const void* p) {
    uint32_t a;
    asm("{ .reg .u64 t; cvta.to.shared.u64 t, %1; cvt.u32.u64 %0, t; }"
        : "=r"(a) : "l"(p));
    return a;
}
#define LDMATRIX_X4(r0, r1, r2, r3, a) \
    asm volatile("ldmatrix.sync.aligned.m8n8.x4.shared.b16 {%0,%1,%2,%3}, [%4];" \
                 : "=r"(r0), "=r"(r1), "=r"(r2), "=r"(r3) : "r"(a))
#define LDMATRIX_X4_TRANS(r0, r1, r2, r3, a) \
    asm volatile("ldmatrix.sync.aligned.m8n8.x4.trans.shared.b16 {%0,%1,%2,%3}, [%4];" \
                 : "=r"(r0), "=r"(r1), "=r"(r2), "=r"(r3) : "r"(a))
#define MMA_BF16(d, a, b) \
    asm volatile("mma.sync.aligned.m16n8k16.row.col.f32.bf16.bf16.f32 " \
                 "{%0,%1,%2,%3}, {%4,%5,%6,%7}, {%8,%9}, {%0,%1,%2,%3};" \
                 : "+f"((d)[0]), "+f"((d)[1]), "+f"((d)[2]), "+f"((d)[3]) \
                 : "r"((a)[0]), "r"((a)[1]), "r"((a)[2]), "r"((a)[3]), \
                   "r"((b)[0]), "r"((b)[1]))
#define CP_ASYNC16(dst, src) \
    asm volatile("cp.async.cg.shared.global [%0], [%1], 16;" :: "r"(dst), "l"(src))
#define CP_COMMIT() asm volatile("cp.async.commit_group;" ::: "memory")
#define CP_WAIT(n)  asm volatile("cp.async.wait_group %0;" :: "n"(n) : "memory")
// Programmatic dependent launch
#define GDC_WAIT()    asm volatile("griddepcontrol.wait;" ::: "memory")
#define GDC_LAUNCH()  asm volatile("griddepcontrol.launch_dependents;" ::: "memory")

__device__ __forceinline__ uint32_t swz(uint32_t off) { return off ^ ((off >> 3) & 0x70); }
__device__ __forceinline__ uint32_t packbf(float a, float b) {
    __nv_bfloat162 h = __floats2bfloat162_rn(a, b);
    return *reinterpret_cast<uint32_t*>(&h);
}
// ff1 permutation: out col n -> source col of ff1_w
__device__ __forceinline__ int ff1_src(int n) {
    const int within = n & 127, blk = n >> 7;
    return (within < 64) ? (blk * 64 + within) : (256 + blk * 64 + within - 64);
}

// ---------------------------------------------------------------------------
// prep_kernel: weight transposes (ff1 permuted) + rmsnorm1+rope, ONE launch.
// ---------------------------------------------------------------------------
__global__ void prep_kernel(const float* __restrict__ w0, __nv_bfloat16* __restrict__ o0,
                            const float* __restrict__ w1, __nv_bfloat16* __restrict__ o1,
                            const float* __restrict__ w2, __nv_bfloat16* __restrict__ o2,
                            const float* __restrict__ w3, __nv_bfloat16* __restrict__ o3,
                            const float* __restrict__ x,  const float* __restrict__ n1w,
                            __nv_bfloat16* __restrict__ h)
{
    const int bx  = blockIdx.x;
    const int tid = threadIdx.x;
    __shared__ float t[32][33];
    __shared__ float red[2][4];

    if (bx < 448) {
        const int wtile = bx >> 3;
        const int k0    = (bx & 7) * 32;
        const float* w; __nv_bfloat16* o; int N, nb; bool perm = false;
        if      (wtile < 24) { w = w0; o = o0; N = QKVN; nb = wtile;      }
        else if (wtile < 32) { w = w1; o = o1; N = CDIM; nb = wtile - 24; }
        else if (wtile < 48) { w = w2; o = o2; N = FFN;  nb = wtile - 32; perm = true; }
        else                 { w = w3; o = o3; N = CDIM; nb = wtile - 48; }

        const int n0 = nb * 32;
        const int s0 = perm ? ff1_src(n0) : n0;
        const int tx = tid & 31, ty = tid >> 5;
        #pragma unroll
        for (int i = 0; i < 32; i += 8)
            t[ty + i][tx] = w[(size_t)(k0 + ty + i) * N + s0 + tx];
        __syncthreads();
        #pragma unroll
        for (int i = 0; i < 32; i += 8)
            o[(size_t)(n0 + ty + i) * GK + k0 + tx] = __float2bfloat16(t[tx][ty + i]);
        GDC_LAUNCH();
        return;
    }

    // ---- rmsnorm1 + rope: 2 tokens per block ----
    const int tok  = (bx - 448) * 2 + (tid >> 7);
    const int i    = tid & 127;
    const int half = tid >> 7;
    float2 v = reinterpret_cast<const float2*>(x + (size_t)tok * CDIM)[i];

    float ss = v.x * v.x + v.y * v.y;
    #pragma unroll
    for (int off = 16; off; off >>= 1)
        ss += __shfl_xor_sync(0xffffffffu, ss, off);
    if ((i & 31) == 0) red[half][i >> 5] = ss;
    __syncthreads();
    const float r = rsqrtf((red[half][0] + red[half][1] + red[half][2] + red[half][3])
                           * (1.0f / CDIM) + 1e-6f);

    const float2 wv = reinterpret_cast<const float2*>(n1w)[i];
    float a = v.x * r * wv.x;
    float b = v.y * r * wv.y;

    const int yy = (tok >> 6) & 63;
    const int xx = tok & 63;
    const int j  = i & 63;
    const float pos = (i < 64) ? (float)yy : (float)xx;
    const float inv = exp2f((float)j * (-13.28771237954945f / 64.0f));
    float c, s;
    sincosf(pos * inv, &s, &c);
    reinterpret_cast<__nv_bfloat162*>(h + (size_t)tok * CDIM)[i] =
        __floats2bfloat162_rn(a * c - b * s, a * s + b * c);
    GDC_LAUNCH();
}

// ---------------------------------------------------------------------------
// Generic mma.sync bf16 GEMM: BM=64, BN=64, 128 threads, ring 32KB.
// mode: 0 = bf16 out, 2 = fp32 +bias+residual
// ---------------------------------------------------------------------------
#define GS_STAGE 16384u
#define SM_SIZE  32768

__global__ __launch_bounds__(128, 5)
void gemm_mma_kernel(const __nv_bfloat16* __restrict__ A,
                     const __nv_bfloat16* __restrict__ Bt,
                     const float* __restrict__ bias,
                     const float* __restrict__ residual,
                     float* __restrict__ C,
                     __nv_bfloat16* __restrict__ Cb,
                     int N, int mode)
{
    GDC_WAIT();
    extern __shared__ __align__(1024) char smem[];
    const uint32_t sb = smem_u32(smem);
    const int tid  = threadIdx.x;
    const int wid  = tid >> 5;
    const int lane = tid & 31;
    const int bm   = blockIdx.y * 64;
    const int bn   = blockIdx.x * 64;
    const int wm   = wid & 1;
    const int wn   = wid >> 1;
    const int lrow = tid >> 3;
    const int lch  = tid & 7;

    #define LOAD_CHUNK(kc, stage) do {                                           \
        const uint32_t s0 = (uint32_t)(stage) * GS_STAGE;                        \
        _Pragma("unroll")                                                        \
        for (int it = 0; it < 4; it++) {                                         \
            const int row = it * 16 + lrow;                                      \
            uint32_t off = swz((uint32_t)row * 128u + (uint32_t)lch * 16u);      \
            CP_ASYNC16(sb + s0 + off,                                            \
                       A  + (size_t)(bm + row) * GK + (kc) * 64 + lch * 8);      \
            CP_ASYNC16(sb + s0 + 8192u + off,                                    \
                       Bt + (size_t)(bn + row) * GK + (kc) * 64 + lch * 8);      \
        }                                                                        \
        CP_COMMIT();                                                             \
    } while (0)

    LOAD_CHUNK(0, 0);
    LOAD_CHUNK(1, 1);

    float acc[2][4][4] = {};
    const int mtx = lane >> 3;
    const int l7  = lane & 7;

    #pragma unroll
    for (int kc = 0; kc < 4; kc++) {
        if (kc < 3) CP_WAIT(1); else CP_WAIT(0);
        __syncthreads();
        const uint32_t sA = sb + (uint32_t)(kc & 1) * GS_STAGE;
        const uint32_t sB = sA + 8192u;

        #pragma unroll
        for (int s16 = 0; s16 < 4; s16++) {
            const int chunk0 = s16 * 2;
            uint32_t af[2][4];
            #pragma unroll
            for (int mt = 0; mt < 2; mt++) {
                const int row   = wm * 32 + mt * 16 + (mtx & 1) * 8 + l7;
                const int chunk = chunk0 + (mtx >> 1);
                LDMATRIX_X4(af[mt][0], af[mt][1], af[mt][2], af[mt][3],
                            sA + swz((uint32_t)row * 128u + (uint32_t)chunk * 16u));
            }
            uint32_t bf[4][2];
            #pragma unroll
            for (int pair = 0; pair < 2; pair++) {
                const int nrow  = wn * 32 + pair * 16 + (mtx >> 1) * 8 + l7;
                const int chunk = chunk0 + (mtx & 1);
                LDMATRIX_X4(bf[pair * 2][0], bf[pair * 2][1],
                            bf[pair * 2 + 1][0], bf[pair * 2 + 1][1],
                            sB + swz((uint32_t)nrow * 128u + (uint32_t)chunk * 16u));
            }
            #pragma unroll
            for (int mt = 0; mt < 2; mt++)
                #pragma unroll
                for (int nt = 0; nt < 4; nt++)
                    MMA_BF16(acc[mt][nt], af[mt], bf[nt]);
        }
        __syncthreads();
        if (kc < 2) LOAD_CHUNK(kc + 2, kc & 1);
    }
    #undef LOAD_CHUNK

    const int rbase = bm + wm * 32 + (lane >> 2);
    const int cbase = bn + wn * 32 + (lane & 3) * 2;
    #pragma unroll
    for (int mt = 0; mt < 2; mt++) {
        #pragma unroll
        for (int half = 0; half < 2; half++) {
            const int row = rbase + mt * 16 + half * 8;
            #pragma unroll
            for (int nt = 0; nt < 4; nt++) {
                const int col = cbase + nt * 8;
                float ox = acc[mt][nt][half * 2];
                float oy = acc[mt][nt][half * 2 + 1];
                const size_t idx = (size_t)row * N + col;
                if (mode == 0) {
                    *reinterpret_cast<__nv_bfloat162*>(&Cb[idx]) =
                        __floats2bfloat162_rn(ox, oy);
                } else {
                    ox += bias[col];
                    oy += bias[col + 1];
                    const float2 rr = *reinterpret_cast<const float2*>(&residual[idx]);
                    *reinterpret_cast<float2*>(&C[idx]) =
                        make_float2(ox + rr.x, oy + rr.y);
                }
            }
        }
    }
    GDC_LAUNCH();
}

// ---------------------------------------------------------------------------
// proj GEMM + residual + fused RMSNorm2 epilogue (R13: BM=32, BN=256,
// 256 threads = 8 warps of 32rows x 32cols, 2-stage ring).
// ---------------------------------------------------------------------------
#define PJ_STG  36864u            // 4KB A + 32KB B per stage
#define PJ_SIZE 73728

__global__ __launch_bounds__(256, 2)
void proj_norm_kernel(const __nv_bfloat16* __restrict__ A,
                      const __nv_bfloat16* __restrict__ Bt,
                      const float* __restrict__ bias,
                      const float* __restrict__ residual,
                      const float* __restrict__ n2w,
                      float* __restrict__ X1,
                      __nv_bfloat16* __restrict__ N2)
{
    GDC_WAIT();
    extern __shared__ __align__(1024) char smem[];
    const uint32_t sb = smem_u32(smem);
    float* sredn = reinterpret_cast<float*>(smem);    // [32][8] (stage0, dead)
    const int tid  = threadIdx.x;
    const int wid  = tid >> 5;                        // wn = wid, 32 cols each
    const int lane = tid & 31;
    const int bm   = blockIdx.x * 32;
    const int lrow = tid >> 3;                        // 0..31
    const int lch  = tid & 7;

    #define PJ_LOAD(kc, stage) do {                                              \
        const uint32_t s0 = (uint32_t)(stage) * PJ_STG;                          \
        {                                                                        \
            uint32_t off = swz((uint32_t)lrow * 128u + (uint32_t)lch * 16u);     \
            CP_ASYNC16(sb + s0 + off,                                            \
                       A + (size_t)(bm + lrow) * GK + (kc) * 64 + lch * 8);      \
        }                                                                        \
        _Pragma("unroll")                                                        \
        for (int it = 0; it < 8; it++) {                                         \
            const int row = it * 32 + lrow;                                      \
            uint32_t off = swz((uint32_t)row * 128u + (uint32_t)lch * 16u);      \
            CP_ASYNC16(sb + s0 + 4096u + off,                                    \
                       Bt + (size_t)row * GK + (kc) * 64 + lch * 8);             \
        }                                                                        \
        CP_COMMIT();                                                             \
    } while (0)

    PJ_LOAD(0, 0);
    PJ_LOAD(1, 1);

    float acc[2][4][4] = {};
    const int mtx = lane >> 3;
    const int l7  = lane & 7;

    #pragma unroll
    for (int kc = 0; kc < 4; kc++) {
        if (kc < 3) CP_WAIT(1); else CP_WAIT(0);
        __syncthreads();
        const uint32_t sA = sb + (uint32_t)(kc & 1) * PJ_STG;
        const uint32_t sB = sA + 4096u;

        #pragma unroll
        for (int s16 = 0; s16 < 4; s16++) {
            const int chunk0 = s16 * 2;
            uint32_t af[2][4];
            #pragma unroll
            for (int mt = 0; mt < 2; mt++) {
                const int row   = mt * 16 + (mtx & 1) * 8 + l7;
                const int chunk = chunk0 + (mtx >> 1);
                LDMATRIX_X4(af[mt][0], af[mt][1], af[mt][2], af[mt][3],
                            sA + swz((uint32_t)row * 128u + (uint32_t)chunk * 16u));
            }
            uint32_t bf[4][2];
            #pragma unroll
            for (int pair = 0; pair < 2; pair++) {
                const int nrow  = wid * 32 + pair * 16 + (mtx >> 1) * 8 + l7;
                const int chunk = chunk0 + (mtx & 1);
                LDMATRIX_X4(bf[pair * 2][0], bf[pair * 2][1],
                            bf[pair * 2 + 1][0], bf[pair * 2 + 1][1],
                            sB + swz((uint32_t)nrow * 128u + (uint32_t)chunk * 16u));
            }
            #pragma unroll
            for (int mt = 0; mt < 2; mt++)
                #pragma unroll
                for (int nt = 0; nt < 4; nt++)
                    MMA_BF16(acc[mt][nt], af[mt], bf[nt]);
        }
        __syncthreads();
        if (kc < 2) PJ_LOAD(kc + 2, kc & 1);
    }
    #undef PJ_LOAD

    // ---- epilogue: bias + residual -> x1; rowwise sumsq across 8 warps ----
    const int rl   = lane >> 2;                  // local row base 0..7
    const int cbse = wid * 32 + (lane & 3) * 2;
    float ss[2][2] = {};
    #pragma unroll
    for (int mt = 0; mt < 2; mt++) {
        #pragma unroll
        for (int half = 0; half < 2; half++) {
            const int row = bm + rl + mt * 16 + half * 8;
            #pragma unroll
            for (int nt = 0; nt < 4; nt++) {
                const int col = cbse + nt * 8;
                float ox = acc[mt][nt][half * 2]     + bias[col];
                float oy = acc[mt][nt][half * 2 + 1] + bias[col + 1];
                const size_t idx = (size_t)row * CDIM + col;
                const float2 rr = *reinterpret_cast<const float2*>(&residual[idx]);
                ox += rr.x; oy += rr.y;
                *reinterpret_cast<float2*>(&X1[idx]) = make_float2(ox, oy);
                acc[mt][nt][half * 2]     = ox;
                acc[mt][nt][half * 2 + 1] = oy;
                ss[mt][half] += ox * ox + oy * oy;
            }
        }
    }
    #pragma unroll
    for (int mt = 0; mt < 2; mt++)
        #pragma unroll
        for (int half = 0; half < 2; half++) {
            float v = ss[mt][half];
            v += __shfl_xor_sync(0xffffffffu, v, 1);
            v += __shfl_xor_sync(0xffffffffu, v, 2);
            if ((lane & 3) == 0)
                sredn[(rl + mt * 16 + half * 8) * 8 + wid] = v;
        }
    __syncthreads();

    #pragma unroll
    for (int mt = 0; mt < 2; mt++) {
        #pragma unroll
        for (int half = 0; half < 2; half++) {
            const int rloc = rl + mt * 16 + half * 8;
            float tot = 0.0f;
            #pragma unroll
            for (int wq = 0; wq < 8; wq++) tot += sredn[rloc * 8 + wq];
            const float r = rsqrtf(tot * (1.0f / CDIM) + 1e-6f);
            const int row = bm + rloc;
            #pragma unroll
            for (int nt = 0; nt < 4; nt++) {
                const int col = cbse + nt * 8;
                const float2 wv = *reinterpret_cast<const float2*>(&n2w[col]);
                *reinterpret_cast<__nv_bfloat162*>(&N2[(size_t)row * CDIM + col]) =
                    __floats2bfloat162_rn(acc[mt][nt][half * 2] * r * wv.x,
                                          acc[mt][nt][half * 2 + 1] * r * wv.y);
            }
        }
    }
    GDC_LAUNCH();
}

// ---------------------------------------------------------------------------
// ff1 GEMM (permuted columns) + bias + fused GeGLU epilogue (R13, 2-stage).
// ---------------------------------------------------------------------------
#define F1_STG  24576u
#define F1_SIZE 49152

__global__ __launch_bounds__(256, 3)
void ff1_geglu_kernel(const __nv_bfloat16* __restrict__ A,
                      const __nv_bfloat16* __restrict__ Bt,
                      const float* __restrict__ bias,
                      __nv_bfloat16* __restrict__ G)
{
    GDC_WAIT();
    extern __shared__ __align__(1024) char smem[];
    const uint32_t sb = smem_u32(smem);
    float* vred = reinterpret_cast<float*>(smem);
    const int tid  = threadIdx.x;
    const int wid  = tid >> 5;
    const int lane = tid & 31;
    const int bm   = blockIdx.y * 64;
    const int bn   = blockIdx.x * 128;
    const int wm   = wid & 1;
    const int wn   = wid >> 1;
    const int lrow = tid >> 3;
    const int lch  = tid & 7;

    #define F1_LOAD(kc, stage) do {                                              \
        const uint32_t s0 = (uint32_t)(stage) * F1_STG;                          \
        _Pragma("unroll")                                                        \
        for (int it = 0; it < 2; it++) {                                         \
            const int row = it * 32 + lrow;                                      \
            uint32_t off = swz((uint32_t)row * 128u + (uint32_t)lch * 16u);      \
            CP_ASYNC16(sb + s0 + off,                                            \
                       A + (size_t)(bm + row) * GK + (kc) * 64 + lch * 8);       \
        }                                                                        \
        _Pragma("unroll")                                                        \
        for (int it = 0; it < 4; it++) {                                         \
            const int row = it * 32 + lrow;                                      \
            uint32_t off = swz((uint32_t)row * 128u + (uint32_t)lch * 16u);      \
            CP_ASYNC16(sb + s0 + 8192u + off,                                    \
                       Bt + (size_t)(bn + row) * GK + (kc) * 64 + lch * 8);      \
        }                                                                        \
        CP_COMMIT();                                                             \
    } while (0)

    F1_LOAD(0, 0);
    F1_LOAD(1, 1);

    float acc[2][4][4] = {};
    const int mtx = lane >> 3;
    const int l7  = lane & 7;

    #pragma unroll
    for (int kc = 0; kc < 4; kc++) {
        if (kc < 3) CP_WAIT(1); else CP_WAIT(0);
        __syncthreads();
        const uint32_t sA = sb + (uint32_t)(kc & 1) * F1_STG;
        const uint32_t sB = sA + 8192u;

        #pragma unroll
        for (int s16 = 0; s16 < 4; s16++) {
            const int chunk0 = s16 * 2;
            uint32_t af[2][4];
            #pragma unroll
            for (int mt = 0; mt < 2; mt++) {
                const int row   = wm * 32 + mt * 16 + (mtx & 1) * 8 + l7;
                const int chunk = chunk0 + (mtx >> 1);
                LDMATRIX_X4(af[mt][0], af[mt][1], af[mt][2], af[mt][3],
                            sA + swz((uint32_t)row * 128u + (uint32_t)chunk * 16u));
            }
            uint32_t bf[4][2];
            #pragma unroll
            for (int pair = 0; pair < 2; pair++) {
                const int nrow  = wn * 32 + pair * 16 + (mtx >> 1) * 8 + l7;
                const int chunk = chunk0 + (mtx & 1);
                LDMATRIX_X4(bf[pair * 2][0], bf[pair * 2][1],
                            bf[pair * 2 + 1][0], bf[pair * 2 + 1][1],
                            sB + swz((uint32_t)nrow * 128u + (uint32_t)chunk * 16u));
            }
            #pragma unroll
            for (int mt = 0; mt < 2; mt++)
                #pragma unroll
                for (int nt = 0; nt < 4; nt++)
                    MMA_BF16(acc[mt][nt], af[mt], bf[nt]);
        }
        __syncthreads();
        if (kc < 2) F1_LOAD(kc + 2, kc & 1);
    }
    #undef F1_LOAD

    const int rl   = wm * 32 + (lane >> 2);
    const int cloc = wn * 32 + (lane & 3) * 2;
    #pragma unroll
    for (int mt = 0; mt < 2; mt++) {
        #pragma unroll
        for (int half = 0; half < 2; half++) {
            #pragma unroll
            for (int nt = 0; nt < 4; nt++) {
                const int c = cloc + nt * 8;
                acc[mt][nt][half * 2]     += bias[ff1_src(bn + c)];
                acc[mt][nt][half * 2 + 1] += bias[ff1_src(bn + c + 1)];
            }
        }
    }
    if (wn >= 2) {
        #pragma unroll
        for (int mt = 0; mt < 2; mt++)
            #pragma unroll
            for (int half = 0; half < 2; half++) {
                const int row = rl + mt * 16 + half * 8;
                #pragma unroll
                for (int nt = 0; nt < 4; nt++) {
                    const int j = cloc + nt * 8 - 64;
                    *reinterpret_cast<float2*>(&vred[row * 64 + j]) =
                        make_float2(acc[mt][nt][half * 2], acc[mt][nt][half * 2 + 1]);
                }
            }
    }
    __syncthreads();
    if (wn < 2) {
        #pragma unroll
        for (int mt = 0; mt < 2; mt++)
            #pragma unroll
            for (int half = 0; half < 2; half++) {
                const int row = rl + mt * 16 + half * 8;
                #pragma unroll
                for (int nt = 0; nt < 4; nt++) {
                    const int j = cloc + nt * 8;
                    const float2 vv = *reinterpret_cast<const float2*>(&vred[row * 64 + j]);
                    const float g0 = acc[mt][nt][half * 2];
                    const float g1 = acc[mt][nt][half * 2 + 1];
                    const float e0 = 0.5f * g0 * (1.0f + erff(g0 * 0.70710678118654752f));
                    const float e1 = 0.5f * g1 * (1.0f + erff(g1 * 0.70710678118654752f));
                    *reinterpret_cast<__nv_bfloat162*>(
                        &G[(size_t)(bm + row) * CDIM + blockIdx.x * 64 + j]) =
                        __floats2bfloat162_rn(e0 * vv.x, e1 * vv.y);
                }
            }
    }
    GDC_LAUNCH();
}

// ---------------------------------------------------------------------------
// Neighborhood attention, 4x8 token tile, halo 10x14 -> 160 kv (R12/R13).
// ---------------------------------------------------------------------------
#define AT_Q    0
#define AT_K    4096
#define AT_V    24576
#define AT_RED  4096
#define AT_MAX  45056
#define AT_SUM  45312
#define AT_SIZE 45568
#define REDW    68

__global__ __launch_bounds__(128, 5)
void attn_mma_kernel(const __nv_bfloat16* __restrict__ qkv,
                     __nv_bfloat16* __restrict__ out)
{
    GDC_WAIT();
    extern __shared__ __align__(1024) char smem[];
    const uint32_t sb = smem_u32(smem);
    float* smax = reinterpret_cast<float*>(smem + AT_MAX);
    float* ssum = reinterpret_cast<float*>(smem + AT_SUM);
    float* sred = reinterpret_cast<float*>(smem + AT_RED);

    const int tid  = threadIdx.x;
    const int wid  = tid >> 5;
    const int lane = tid & 31;
    const int head = blockIdx.y;
    const int b    = blockIdx.z;
    const int ty0  = (blockIdx.x >> 3) * 4;
    const int tx0  = (blockIdx.x & 7) * 8;
    const int ny0  = min(max(ty0 - 3, 0), 54);
    const int nx0  = min(max(tx0 - 3, 0), 50);

    const __nv_bfloat16* base = qkv + (size_t)b * 4096 * QKVN + head * 64;

    #pragma unroll
    for (int i = 0; i < 2; i++) {
        const int idx = i * 128 + tid;
        const int m = idx >> 3, ch = idx & 7;
        const int y = ty0 + (m >> 3), x = tx0 + (m & 7);
        uint32_t off = swz((uint32_t)m * 128u + (uint32_t)ch * 16u);
        CP_ASYNC16(sb + AT_Q + off, base + (size_t)(y * 64 + x) * QKVN + ch * 8);
    }
    CP_COMMIT();
    #pragma unroll
    for (int i = 0; i < 10; i++) {
        const int idx = i * 128 + tid;
        const int kv = idx >> 3, ch = idx & 7;
        const int r = kv >> 4, c = kv & 15;
        uint32_t off = swz((uint32_t)kv * 128u + (uint32_t)ch * 16u);
        if (c < 14)
            CP_ASYNC16(sb + AT_K + off,
                       base + (size_t)((ny0 + r) * 64 + nx0 + c) * QKVN + CDIM + ch * 8);
        else
            *reinterpret_cast<uint4*>(smem + AT_K + off) = make_uint4(0, 0, 0, 0);
    }
    CP_COMMIT();
    #pragma unroll
    for (int i = 0; i < 10; i++) {
        const int idx = i * 128 + tid;
        const int kv = idx >> 3, ch = idx & 7;
        const int r = kv >> 4, c = kv & 15;
        uint32_t off = swz((uint32_t)kv * 128u + (uint32_t)ch * 16u);
        if (c < 14)
            CP_ASYNC16(sb + AT_V + off,
                       base + (size_t)((ny0 + r) * 64 + nx0 + c) * QKVN + 2 * CDIM + ch * 8);
        else
            *reinterpret_cast<uint4*>(smem + AT_V + off) = make_uint4(0, 0, 0, 0);
    }
    CP_COMMIT();

    const int wm  = wid & 1;
    const int wn  = wid >> 1;
    const int mtx = lane >> 3;
    const int l7  = lane & 7;

    CP_WAIT(1);
    __syncthreads();

    uint32_t af[4][4];
    #pragma unroll
    for (int k16 = 0; k16 < 4; k16++) {
        const int row   = wm * 16 + (mtx & 1) * 8 + l7;
        const int chunk = k16 * 2 + (mtx >> 1);
        LDMATRIX_X4(af[k16][0], af[k16][1], af[k16][2], af[k16][3],
                    sb + AT_Q + swz((uint32_t)row * 128u + (uint32_t)chunk * 16u));
    }

    float acc[10][4] = {};
    #pragma unroll
    for (int k16 = 0; k16 < 4; k16++) {
        #pragma unroll
        for (int pair = 0; pair < 5; pair++) {
            const int nrow  = wn * 80 + pair * 16 + (mtx >> 1) * 8 + l7;
            const int chunk = k16 * 2 + (mtx & 1);
            uint32_t b0, b1, b2, b3;
            LDMATRIX_X4(b0, b1, b2, b3,
                        sb + AT_K + swz((uint32_t)nrow * 128u + (uint32_t)chunk * 16u));
            uint32_t bfa[2] = {b0, b1}, bfb[2] = {b2, b3};
            MMA_BF16(acc[pair * 2],     af[k16], bfa);
            MMA_BF16(acc[pair * 2 + 1], af[k16], bfb);
        }
    }

    const int row0 = wm * 16 + (lane >> 2);
    const int row1 = row0 + 8;
    const int y_a = ty0 + (row0 >> 3), x_a = tx0 + (row0 & 7);
    const int y_b = ty0 + (row1 >> 3), x_b = tx0 + (row1 & 7);
    const int rlo_a = min(max(y_a - 3, 0), 57) - ny0;
    const int clo_a = min(max(x_a - 3, 0), 57) - nx0;
    const int rlo_b = min(max(y_b - 3, 0), 57) - ny0;
    const int clo_b = min(max(x_b - 3, 0), 57) - nx0;

    uint32_t vm_a = 0, vm_b = 0;
    #pragma unroll
    for (int nt = 0; nt < 10; nt++) {
        #pragma unroll
        for (int j = 0; j < 2; j++) {
            const int n = wn * 80 + nt * 8 + (lane & 3) * 2 + j;
            const int r = n >> 4, c = n & 15;
            if (c < 14 && (unsigned)(r - rlo_a) < 7u && (unsigned)(c - clo_a) < 7u)
                vm_a |= 1u << (nt * 2 + j);
            if (c < 14 && (unsigned)(r - rlo_b) < 7u && (unsigned)(c - clo_b) < 7u)
                vm_b |= 1u << (nt * 2 + j);
        }
    }

    float mx_a = -3e38f, mx_b = -3e38f;
    #pragma unroll
    for (int nt = 0; nt < 10; nt++) {
        #pragma unroll
        for (int j = 0; j < 2; j++) {
            if (vm_a & (1u << (nt * 2 + j))) mx_a = fmaxf(mx_a, acc[nt][j]);
            if (vm_b & (1u << (nt * 2 + j))) mx_b = fmaxf(mx_b, acc[nt][2 + j]);
        }
    }
    mx_a = fmaxf(mx_a, __shfl_xor_sync(0xffffffffu, mx_a, 1));
    mx_a = fmaxf(mx_a, __shfl_xor_sync(0xffffffffu, mx_a, 2));
    mx_b = fmaxf(mx_b, __shfl_xor_sync(0xffffffffu, mx_b, 1));
    mx_b = fmaxf(mx_b, __shfl_xor_sync(0xffffffffu, mx_b, 2));
    if ((lane & 3) == 0) {
        smax[row0 * 2 + wn] = mx_a;
        smax[row1 * 2 + wn] = mx_b;
    }
    __syncthreads();
    const float M_a = fmaxf(smax[row0 * 2], smax[row0 * 2 + 1]);
    const float M_b = fmaxf(smax[row1 * 2], smax[row1 * 2 + 1]);

    const float SC = 0.18033688011112042f;
    float sm_a = 0.0f, sm_b = 0.0f;
    #pragma unroll
    for (int nt = 0; nt < 10; nt++) {
        #pragma unroll
        for (int j = 0; j < 2; j++) {
            float ea = (vm_a & (1u << (nt * 2 + j)))
                     ? exp2f((acc[nt][j] - M_a) * SC) : 0.0f;
            float eb = (vm_b & (1u << (nt * 2 + j)))
                     ? exp2f((acc[nt][2 + j] - M_b) * SC) : 0.0f;
            acc[nt][j] = ea; acc[nt][2 + j] = eb;
            sm_a += ea; sm_b += eb;
        }
    }
    sm_a += __shfl_xor_sync(0xffffffffu, sm_a, 1);
    sm_a += __shfl_xor_sync(0xffffffffu, sm_a, 2);
    sm_b += __shfl_xor_sync(0xffffffffu, sm_b, 1);
    sm_b += __shfl_xor_sync(0xffffffffu, sm_b, 2);
    if ((lane & 3) == 0) {
        ssum[row0 * 2 + wn] = sm_a;
        ssum[row1 * 2 + wn] = sm_b;
    }

    uint32_t pf[5][4];
    #pragma unroll
    for (int s = 0; s < 5; s++) {
        pf[s][0] = packbf(acc[2 * s][0],     acc[2 * s][1]);
        pf[s][1] = packbf(acc[2 * s][2],     acc[2 * s][3]);
        pf[s][2] = packbf(acc[2 * s + 1][0], acc[2 * s + 1][1]);
        pf[s][3] = packbf(acc[2 * s + 1][2], acc[2 * s + 1][3]);
    }

    CP_WAIT(0);
    __syncthreads();

    float accO[8][4] = {};
    #pragma unroll
    for (int s = 0; s < 5; s++) {
        uint32_t vf[8][2];
        #pragma unroll
        for (int g2 = 0; g2 < 4; g2++) {
            const int kvrow = wn * 80 + s * 16 + (lane & 15);
            const int colb  = (g2 * 16 + (lane >> 4) * 8) * 2;
            LDMATRIX_X4_TRANS(vf[g2 * 2][0], vf[g2 * 2][1],
                              vf[g2 * 2 + 1][0], vf[g2 * 2 + 1][1],
                              sb + AT_V + swz((uint32_t)kvrow * 128u + (uint32_t)colb));
        }
        #pragma unroll
        for (int nt = 0; nt < 8; nt++)
            MMA_BF16(accO[nt], pf[s], vf[nt]);
    }

    if (wn == 1) {
        #pragma unroll
        for (int nt = 0; nt < 8; nt++) {
            const int col = nt * 8 + (lane & 3) * 2;
            *reinterpret_cast<float2*>(&sred[row0 * REDW + col]) =
                make_float2(accO[nt][0], accO[nt][1]);
            *reinterpret_cast<float2*>(&sred[row1 * REDW + col]) =
                make_float2(accO[nt][2], accO[nt][3]);
        }
    }
    __syncthreads();

    if (wn == 0) {
        const float inv_a = 1.0f / (ssum[row0 * 2] + ssum[row0 * 2 + 1]);
        const float inv_b = 1.0f / (ssum[row1 * 2] + ssum[row1 * 2 + 1]);
        const size_t t_a = (size_t)b * 4096 + (size_t)(y_a * 64 + x_a);
        const size_t t_b = (size_t)b * 4096 + (size_t)(y_b * 64 + x_b);
        #pragma unroll
        for (int nt = 0; nt < 8; nt++) {
            const int col = nt * 8 + (lane & 3) * 2;
            const float2 ra = *reinterpret_cast<const float2*>(&sred[row0 * REDW + col]);
            const float2 rb = *reinterpret_cast<const float2*>(&sred[row1 * REDW + col]);
            *reinterpret_cast<__nv_bfloat162*>(out + t_a * CDIM + head * 64 + col) =
                __floats2bfloat162_rn((accO[nt][0] + ra.x) * inv_a,
                                      (accO[nt][1] + ra.y) * inv_a);
            *reinterpret_cast<__nv_bfloat162*>(out + t_b * CDIM + head * 64 + col) =
                __floats2bfloat162_rn((accO[nt][2] + rb.x) * inv_b,
                                      (accO[nt][3] + rb.y) * inv_b);
        }
    }
    GDC_LAUNCH();
}

// ---------------------------------------------------------------------------
// Launch: 6 kernels, PDL-chained.
// ---------------------------------------------------------------------------
extern "C" void kernel_launch(void* const* d_in, const int* in_sizes, int n_in,
                              void* d_out, int out_size)
{
    const float* x       = (const float*)d_in[0];
    const float* norm1_w = (const float*)d_in[1];
    const float* norm2_w = (const float*)d_in[2];
    const float* w_qkv   = (const float*)d_in[3];
    const float* w_proj  = (const float*)d_in[4];
    const float* b_proj  = (const float*)d_in[5];
    const float* ff1_w   = (const float*)d_in[6];
    const float* ff1_b   = (const float*)d_in[7];
    const float* ff2_w   = (const float*)d_in[8];
    const float* ff2_b   = (const float*)d_in[9];
    float* out = (float*)d_out;

    __nv_bfloat16 *p_h, *p_qkv, *p_attn, *p_n2, *p_g;
    __nv_bfloat16 *p_wqkvT, *p_wprojT, *p_ff1T, *p_ff2T;
    float *p_x1;
    cudaGetSymbolAddress((void**)&p_h,      g_h);
    cudaGetSymbolAddress((void**)&p_qkv,    g_qkv);
    cudaGetSymbolAddress((void**)&p_attn,   g_attn);
    cudaGetSymbolAddress((void**)&p_x1,     g_x1);
    cudaGetSymbolAddress((void**)&p_n2,     g_n2);
    cudaGetSymbolAddress((void**)&p_g,      g_g);
    cudaGetSymbolAddress((void**)&p_wqkvT,  g_wqkvT);
    cudaGetSymbolAddress((void**)&p_wprojT, g_wprojT);
    cudaGetSymbolAddress((void**)&p_ff1T,   g_ff1T);
    cudaGetSymbolAddress((void**)&p_ff2T,   g_ff2T);

    cudaFuncSetAttribute(gemm_mma_kernel,
                         cudaFuncAttributeMaxDynamicSharedMemorySize, SM_SIZE);
    cudaFuncSetAttribute(proj_norm_kernel,
                         cudaFuncAttributeMaxDynamicSharedMemorySize, PJ_SIZE);
    cudaFuncSetAttribute(ff1_geglu_kernel,
                         cudaFuncAttributeMaxDynamicSharedMemorySize, F1_SIZE);
    cudaFuncSetAttribute(attn_mma_kernel,
                         cudaFuncAttributeMaxDynamicSharedMemorySize, AT_SIZE);

    cudaLaunchAttribute pdl[1];
    pdl[0].id = cudaLaunchAttributeProgrammaticStreamSerialization;
    pdl[0].val.programmaticStreamSerializationAllowed = 1;

    // 1. weight transposes (ff1 permuted) + rmsnorm1+rope
    prep_kernel<<<448 + NTOK / 2, 256>>>(
        w_qkv, p_wqkvT, w_proj, p_wprojT, ff1_w, p_ff1T, ff2_w, p_ff2T,
        x, norm1_w, p_h);

    // 2. qkv = h @ w_qkv -> bf16   (PDL on prep)
    {
        cudaLaunchConfig_t cfg = {};
        cfg.gridDim  = dim3(QKVN / 64, NTOK / 64);
        cfg.blockDim = dim3(128);
        cfg.dynamicSmemBytes = SM_SIZE;
        cfg.stream = 0;
        cfg.attrs = pdl; cfg.numAttrs = 1;
        cudaLaunchKernelEx(&cfg, gemm_mma_kernel,
                           (const __nv_bfloat16*)p_h, (const __nv_bfloat16*)p_wqkvT,
                           (const float*)nullptr, (const float*)nullptr,
                           (float*)nullptr, p_qkv, (int)QKVN, 0);
    }

    // 3. attention (4x8 tiles) -> bf16   (PDL on qkv)
    {
        cudaLaunchConfig_t cfg = {};
        cfg.gridDim  = dim3(128, 4, 2);
        cfg.blockDim = dim3(128);
        cfg.dynamicSmemBytes = AT_SIZE;
        cfg.stream = 0;
        cfg.attrs = pdl; cfg.numAttrs = 1;
        cudaLaunchKernelEx(&cfg, attn_mma_kernel,
                           (const __nv_bfloat16*)p_qkv, p_attn);
    }

    // 4. x1 = x + attn @ w_proj + b_proj; n2 = rmsnorm(x1)   (PDL on attn)
    {
        cudaLaunchConfig_t cfg = {};
        cfg.gridDim  = dim3(NTOK / 32);
        cfg.blockDim = dim3(256);
        cfg.dynamicSmemBytes = PJ_SIZE;
        cfg.stream = 0;
        cfg.attrs = pdl; cfg.numAttrs = 1;
        cudaLaunchKernelEx(&cfg, proj_norm_kernel,
                           (const __nv_bfloat16*)p_attn, (const __nv_bfloat16*)p_wprojT,
                           b_proj, x, norm2_w, p_x1, p_n2);
    }

    // 5. g = geglu(n2 @ ff1_w_perm + ff1_b)   (PDL on proj)
    {
        cudaLaunchConfig_t cfg = {};
        cfg.gridDim  = dim3(4, NTOK / 64);
        cfg.blockDim = dim3(256);
        cfg.dynamicSmemBytes = F1_SIZE;
        cfg.stream = 0;
        cfg.attrs = pdl; cfg.numAttrs = 1;
        cudaLaunchKernelEx(&cfg, ff1_geglu_kernel,
                           (const __nv_bfloat16*)p_n2, (const __nv_bfloat16*)p_ff1T,
                           ff1_b, p_g);
    }

    // 6. out = x1 + g @ ff2_w + ff2_b   (PDL on ff1)
    {
        cudaLaunchConfig_t cfg = {};
        cfg.gridDim  = dim3(CDIM / 64, NTOK / 64);
        cfg.blockDim = dim3(128);
        cfg.dynamicSmemBytes = SM_SIZE;
        cfg.stream = 0;
        cfg.attrs = pdl; cfg.numAttrs = 1;
        cudaLaunchKernelEx(&cfg, gemm_mma_kernel,
                           (const __nv_bfloat16*)p_g, (const __nv_bfloat16*)p_ff2T,
                           ff2_b, (const float*)p_x1,
                           out, (__nv_bfloat16*)nullptr, (int)CDIM, 2);
    }
}